// round 12
// baseline (speedup 1.0000x reference)
#include <cuda_runtime.h>
#include <cuda_bf16.h>
#include <math.h>
#include <stdint.h>

#define BB 8
#define NN 4096
#define MM 4096
#define DD 128
#define NTILES 32          // 4096 / 128 tiles along each reduced dim

// ---------------- scratch (device globals: no allocation allowed) ----------
__device__ __nv_bfloat16 g_hi0[BB * NN * DD];
__device__ __nv_bfloat16 g_lo0[BB * NN * DD];
__device__ __nv_bfloat16 g_hi1[BB * MM * DD];
__device__ __nv_bfloat16 g_lo1[BB * MM * DD];

__device__ float2 g_rp_v[BB * NN * NTILES];
__device__ int2   g_rp_i[BB * NN * NTILES];
__device__ float2 g_cp_v[BB * MM * NTILES];
__device__ int2   g_cp_i[BB * MM * NTILES];

__device__ int    g_m0raw[BB * NN];
__device__ int    g_m1raw[BB * MM];

// ---------------- small helpers ---------------------------------------------
__device__ __forceinline__ void push2(float v, int i,
                                      float& v0, int& i0, float& v1, int& i1) {
    if (v > v0) { v1 = v0; i1 = i0; v0 = v; i0 = i; }
    else if (v > v1) { v1 = v; i1 = i; }
}

__device__ __forceinline__ bool better(float va, int ia, float vb, int ib) {
    return (va > vb) || (va == vb && ia < ib);
}

__device__ __forceinline__ void merge2(float& v0, int& i0, float& v1, int& i1,
                                       float ov0, int oi0, float ov1, int oi1) {
    if (better(ov0, oi0, v0, i0)) {
        if (better(v0, i0, ov1, oi1)) { v1 = v0; i1 = i0; }
        else                          { v1 = ov1; i1 = oi1; }
        v0 = ov0; i0 = oi0;
    } else {
        if (better(ov0, oi0, v1, i1)) { v1 = ov0; i1 = oi0; }
    }
}

__device__ __forceinline__ uint32_t smem_u32(const void* p) {
    uint32_t a;
    asm("{ .reg .u64 t; cvta.to.shared.u64 t, %1; cvt.u32.u64 %0, t; }"
        : "=r"(a) : "l"(p));
    return a;
}

__device__ __forceinline__ void ldsm_x4(uint32_t& r0, uint32_t& r1,
                                        uint32_t& r2, uint32_t& r3,
                                        uint32_t addr) {
    asm volatile(
        "ldmatrix.sync.aligned.m8n8.x4.shared.b16 {%0, %1, %2, %3}, [%4];"
        : "=r"(r0), "=r"(r1), "=r"(r2), "=r"(r3) : "r"(addr));
}

__device__ __forceinline__ void mma_bf16(float& c0, float& c1, float& c2, float& c3,
                                         uint32_t a0, uint32_t a1, uint32_t a2, uint32_t a3,
                                         uint32_t b0, uint32_t b1) {
    asm volatile(
        "mma.sync.aligned.m16n8k16.row.col.f32.bf16.bf16.f32 "
        "{%0, %1, %2, %3}, {%4, %5, %6, %7}, {%8, %9}, {%0, %1, %2, %3};"
        : "+f"(c0), "+f"(c1), "+f"(c2), "+f"(c3)
        : "r"(a0), "r"(a1), "r"(a2), "r"(a3), "r"(b0), "r"(b1));
}

__device__ __forceinline__ void cp_async16(uint32_t saddr, const void* gaddr) {
    asm volatile("cp.async.cg.shared.global [%0], [%1], 16;"
                 :: "r"(saddr), "l"(gaddr));
}
#define CP_COMMIT() asm volatile("cp.async.commit_group;" ::: "memory")
#define CP_WAIT0()  asm volatile("cp.async.wait_group 0;" ::: "memory")
#define CP_WAIT1()  asm volatile("cp.async.wait_group 1;" ::: "memory")

// ---------------- 1. normalize + hi/lo bf16 split -----------------------------
__global__ void normsplit_k(const float* __restrict__ d0,
                            const float* __restrict__ d1) {
    int warp = (blockIdx.x * blockDim.x + threadIdx.x) >> 5;
    int lane = threadIdx.x & 31;
    const int total = BB * NN + BB * MM;
    if (warp >= total) return;

    const float* src;
    __nv_bfloat16 *hid, *lod;
    if (warp < BB * NN) {
        src = d0 + (size_t)warp * DD;
        hid = g_hi0 + (size_t)warp * DD;
        lod = g_lo0 + (size_t)warp * DD;
    } else {
        int w = warp - BB * NN;
        src = d1 + (size_t)w * DD;
        hid = g_hi1 + (size_t)w * DD;
        lod = g_lo1 + (size_t)w * DD;
    }

    float4 v = *(const float4*)(src + lane * 4);
    float s = v.x * v.x + v.y * v.y + v.z * v.z + v.w * v.w;
#pragma unroll
    for (int off = 16; off > 0; off >>= 1)
        s += __shfl_xor_sync(0xFFFFFFFFu, s, off);
    float inv = 1.0f / fmaxf(sqrtf(s), 1e-12f);

    float x[4] = { v.x * inv, v.y * inv, v.z * inv, v.w * inv };
    __nv_bfloat16 h[4], l[4];
#pragma unroll
    for (int e = 0; e < 4; e++) {
        h[e] = __float2bfloat16(x[e]);
        l[e] = __float2bfloat16(x[e] - __bfloat162float(h[e]));
    }
    ((__nv_bfloat162*)(hid + lane * 4))[0] = __nv_bfloat162(h[0], h[1]);
    ((__nv_bfloat162*)(hid + lane * 4))[1] = __nv_bfloat162(h[2], h[3]);
    ((__nv_bfloat162*)(lod + lane * 4))[0] = __nv_bfloat162(l[0], l[1]);
    ((__nv_bfloat162*)(lod + lane * 4))[1] = __nv_bfloat162(l[2], l[3]);
}

// ---------------- 2. mma.sync GEMM tile + fused top-2 -------------------------
// One CTA = one 128x128 sim tile. 256 threads = 8 warps (2 x 4), 64x32 per warp.
// K=128 in four chunks of 32, 2-stage cp.async double-buffer: chunk c+1 loads
// overlap chunk c compute. SMEM/stage: 4 tiles x 128 rows x 80B = 40KB; two
// stages = 80KB -> 2 CTAs/SM. Fragments loaded once per k-step, shared across
// the 3 precision passes (hi*hi, hi*lo, lo*hi).
#define KC   32            // K per chunk
#define NCH  (DD / KC)     // 4 chunks
#define RS   80            // bytes per smem tile row (32 bf16 = 64B + 16B pad)
#define TILE_B (128 * RS)  // 10240 B per operand tile
#define STAGE_B (4 * TILE_B)          // 40960 B per stage
#define OFF_AH 0
#define OFF_AL TILE_B
#define OFF_BH (2 * TILE_B)
#define OFF_BL (3 * TILE_B)
#define SMEM_BYTES (2 * STAGE_B)      // 81920
#define DSTR 130                       // fp32 staging row stride (floats)

__global__ __launch_bounds__(256, 2)
void gemm_tc_k(float* __restrict__ C) {
    extern __shared__ char smem[];
    uint32_t sb = smem_u32(smem);

    const int b     = blockIdx.z;
    const int tileN = blockIdx.y;
    const int tileM = blockIdx.x;
    const int n0 = tileN * 128;    // sim row block   (A side, d0)
    const int m0 = tileM * 128;    // sim col block   (B side, d1)

    const int tid  = threadIdx.x;
    const int wid  = tid >> 5;
    const int lane = tid & 31;
    const int wm   = wid >> 2;     // 0..1 : 64-row band
    const int wn   = wid & 3;      // 0..3 : 32-col band
    const int g    = lane >> 2;    // group id
    const int t    = lane & 3;     // thread-in-group
    const int tile8 = lane >> 3;
    const int r8    = lane & 7;

    // lane-constant ldmatrix offsets (bytes) within a tile
    const uint32_t aoff = (uint32_t)(wm * 64 + (tile8 & 1) * 8 + r8) * RS
                        + (uint32_t)((tile8 >> 1) * 8) * 2;
    const uint32_t boff = (uint32_t)(wn * 32 + ((tile8 >> 1) & 1) * 8 + r8) * RS
                        + (uint32_t)((tile8 & 1) * 8) * 2;

    float acc[4][4][4];            // [mi][ni][c]
#pragma unroll
    for (int mi = 0; mi < 4; mi++)
#pragma unroll
        for (int ni = 0; ni < 4; ni++)
#pragma unroll
            for (int c = 0; c < 4; c++) acc[mi][ni][c] = 0.0f;

    const char* srcs[4] = {
        (const char*)(g_hi0 + ((size_t)b * NN + n0) * DD),
        (const char*)(g_lo0 + ((size_t)b * NN + n0) * DD),
        (const char*)(g_hi1 + ((size_t)b * MM + m0) * DD),
        (const char*)(g_lo1 + ((size_t)b * MM + m0) * DD)
    };

    // per-thread load coords: 2048 16B slots per chunk / 256 threads = 8
    // slot f: tile tt = f >> 9, row = (f >> 2) & 127, q = f & 3
    const int lrow = (tid >> 2) & 63;   // we iterate tt and row-halves below

    // chunk loader: chunk kc into stage st
    auto load_chunk = [&](int kc, int st) {
        const uint32_t sbase = sb + st * STAGE_B;
        const int kgb = kc * KC * 2;     // byte offset along K
#pragma unroll
        for (int tt = 0; tt < 4; tt++) {
#pragma unroll
            for (int half = 0; half < 2; half++) {
                int f   = half * 256 + tid;     // 512 slots per tile
                int row = f >> 2;
                int q   = f & 3;
                cp_async16(sbase + tt * TILE_B + row * RS + q * 16,
                           srcs[tt] + (size_t)row * (DD * 2) + kgb + q * 16);
            }
        }
        CP_COMMIT();
    };
    (void)lrow;

    // prologue
    load_chunk(0, 0);

    for (int kc = 0; kc < NCH; kc++) {
        const int st = kc & 1;
        if (kc + 1 < NCH) {
            load_chunk(kc + 1, (kc + 1) & 1);
            CP_WAIT1();                 // chunk kc done, kc+1 may fly
        } else {
            CP_WAIT0();
        }
        __syncthreads();

        const uint32_t sbase = sb + st * STAGE_B;

        // ---- 2 k-steps of 16; fragments shared across 3 precision passes ----
#pragma unroll
        for (int ks = 0; ks < 2; ks++) {
            const uint32_t kb = ks * 32;   // byte offset of this k-step

            // A_hi fragments
            uint32_t a[4][4];
#pragma unroll
            for (int mi = 0; mi < 4; mi++)
                ldsm_x4(a[mi][0], a[mi][1], a[mi][2], a[mi][3],
                        sbase + OFF_AH + aoff + mi * (16 * RS) + kb);

            // B_hi fragments
            uint32_t bh[4][2];
#pragma unroll
            for (int nh = 0; nh < 2; nh++) {
                uint32_t r0, r1, r2, r3;
                ldsm_x4(r0, r1, r2, r3,
                        sbase + OFF_BH + boff + nh * (16 * RS) + kb);
                bh[nh * 2 + 0][0] = r0; bh[nh * 2 + 0][1] = r1;
                bh[nh * 2 + 1][0] = r2; bh[nh * 2 + 1][1] = r3;
            }

            // pass 0: hi * hi
#pragma unroll
            for (int mi = 0; mi < 4; mi++)
#pragma unroll
                for (int ni = 0; ni < 4; ni++)
                    mma_bf16(acc[mi][ni][0], acc[mi][ni][1],
                             acc[mi][ni][2], acc[mi][ni][3],
                             a[mi][0], a[mi][1], a[mi][2], a[mi][3],
                             bh[ni][0], bh[ni][1]);

            // B_lo fragments
            uint32_t bl[4][2];
#pragma unroll
            for (int nh = 0; nh < 2; nh++) {
                uint32_t r0, r1, r2, r3;
                ldsm_x4(r0, r1, r2, r3,
                        sbase + OFF_BL + boff + nh * (16 * RS) + kb);
                bl[nh * 2 + 0][0] = r0; bl[nh * 2 + 0][1] = r1;
                bl[nh * 2 + 1][0] = r2; bl[nh * 2 + 1][1] = r3;
            }

            // pass 1: hi * lo
#pragma unroll
            for (int mi = 0; mi < 4; mi++)
#pragma unroll
                for (int ni = 0; ni < 4; ni++)
                    mma_bf16(acc[mi][ni][0], acc[mi][ni][1],
                             acc[mi][ni][2], acc[mi][ni][3],
                             a[mi][0], a[mi][1], a[mi][2], a[mi][3],
                             bl[ni][0], bl[ni][1]);

            // A_lo fragments (reuse a[])
#pragma unroll
            for (int mi = 0; mi < 4; mi++)
                ldsm_x4(a[mi][0], a[mi][1], a[mi][2], a[mi][3],
                        sbase + OFF_AL + aoff + mi * (16 * RS) + kb);

            // pass 2: lo * hi
#pragma unroll
            for (int mi = 0; mi < 4; mi++)
#pragma unroll
                for (int ni = 0; ni < 4; ni++)
                    mma_bf16(acc[mi][ni][0], acc[mi][ni][1],
                             acc[mi][ni][2], acc[mi][ni][3],
                             a[mi][0], a[mi][1], a[mi][2], a[mi][3],
                             bh[ni][0], bh[ni][1]);
        }
        __syncthreads();   // stage st free for chunk kc+2's cp.async
    }

    // ---- stage accumulators to SMEM (fp32, stride DSTR) -----------------------
    float* dsm = (float*)smem;
#pragma unroll
    for (int mi = 0; mi < 4; mi++) {
        int r0 = wm * 64 + mi * 16 + g;
#pragma unroll
        for (int ni = 0; ni < 4; ni++) {
            int c0 = wn * 32 + ni * 8 + 2 * t;
            *(float2*)&dsm[r0 * DSTR + c0] =
                make_float2(acc[mi][ni][0], acc[mi][ni][1]);
            *(float2*)&dsm[(r0 + 8) * DSTR + c0] =
                make_float2(acc[mi][ni][2], acc[mi][ni][3]);
        }
    }
    __syncthreads();

    // ---- parallel reductions: threads 0-127 columns, 128-255 rows -------------
    if (tid < 128) {
        int col = tid;                       // sim column m0+col
        float v0 = -2.0f, v1 = -2.0f;
        int   i0 = -1,    i1 = -1;
#pragma unroll 4
        for (int r = 0; r < 128; r++)
            push2(dsm[r * DSTR + col], n0 + r, v0, i0, v1, i1);
        size_t o = ((size_t)b * MM + m0 + col) * NTILES + tileN;
        g_cp_v[o] = make_float2(v0, v1);
        g_cp_i[o] = make_int2(i0, i1);
    } else {
        int row = tid - 128;                 // sim row n0+row
        float v0 = -2.0f, v1 = -2.0f;
        int   i0 = -1,    i1 = -1;
#pragma unroll 4
        for (int c = 0; c < 128; c += 2) {
            float2 v = *(const float2*)&dsm[row * DSTR + c];
            push2(v.x, m0 + c,     v0, i0, v1, i1);
            push2(v.y, m0 + c + 1, v0, i0, v1, i1);
        }
        size_t o = ((size_t)b * NN + n0 + row) * NTILES + tileM;
        g_rp_v[o] = make_float2(v0, v1);
        g_rp_i[o] = make_int2(i0, i1);
    }

    // ---- coalesced sim write (float2) -----------------------------------------
    {
        float* Cb = C + (size_t)b * NN * MM + (size_t)n0 * MM + m0;
#pragma unroll
        for (int it = 0; it < 32; it++) {
            int f   = it * 256 + tid;        // 8192 float2 slots
            int row = f >> 6;                // 64 float2 per row
            int u   = f & 63;
            float2 v = *(const float2*)&dsm[row * DSTR + u * 2];
            *(float2*)(Cb + (size_t)row * MM + u * 2) = v;
        }
    }
}

// ---------------- 3. merge partials + thresholds ------------------------------
__global__ void merge_k() {
    int warp = (blockIdx.x * blockDim.x + threadIdx.x) >> 5;
    int lane = threadIdx.x & 31;
    const int nrows = BB * NN;
    if (warp >= nrows + BB * MM) return;

    float2 pv;
    int2   pi;
    if (warp < nrows) {
        pv = g_rp_v[(size_t)warp * NTILES + lane];
        pi = g_rp_i[(size_t)warp * NTILES + lane];
    } else {
        size_t w = warp - nrows;
        pv = g_cp_v[w * NTILES + lane];
        pi = g_cp_i[w * NTILES + lane];
    }
    float v0 = pv.x, v1 = pv.y;
    int   i0 = pi.x, i1 = pi.y;
#pragma unroll
    for (int off = 16; off > 0; off >>= 1) {
        float ov0 = __shfl_xor_sync(0xFFFFFFFFu, v0, off);
        float ov1 = __shfl_xor_sync(0xFFFFFFFFu, v1, off);
        int   oi0 = __shfl_xor_sync(0xFFFFFFFFu, i0, off);
        int   oi1 = __shfl_xor_sync(0xFFFFFFFFu, i1, off);
        merge2(v0, i0, v1, i1, ov0, oi0, ov1, oi1);
    }
    if (lane == 0) {
        float d0 = 2.0f * (1.0f - v0);
        float d1 = 2.0f * (1.0f - v1);
        bool ok = (d0 <= 0.64f * d1) && (d0 <= 0.49f);
        int m = ok ? i0 : -1;
        if (warp < nrows) g_m0raw[warp] = m;
        else              g_m1raw[warp - nrows] = m;
    }
}

// ---------------- 4. mutual check + output write -----------------------------
// out layout (fp32): matches0 [B*N] | matches1 [B*M] | mscores0 | mscores1 | sim
__global__ void mutual_k(float* __restrict__ out) {
    int idx = blockIdx.x * blockDim.x + threadIdx.x;
    if (idx >= BB * NN) return;
    int b = idx / NN;
    int n = idx - b * NN;

    int m0 = g_m0raw[idx];
    bool good0 = (m0 > -1) && (g_m1raw[b * MM + m0] == n);
    out[idx] = good0 ? (float)m0 : -1.0f;
    out[2 * BB * NN + idx] = good0 ? 1.0f : 0.0f;

    int m1 = g_m1raw[idx];
    bool good1 = (m1 > -1) && (g_m0raw[b * NN + m1] == n);
    out[BB * NN + idx] = good1 ? (float)m1 : -1.0f;
    out[3 * BB * NN + idx] = good1 ? 1.0f : 0.0f;
}

// ---------------- launch -----------------------------------------------------
extern "C" void kernel_launch(void* const* d_in, const int* in_sizes, int n_in,
                              void* d_out, int out_size) {
    const float* desc0 = (const float*)d_in[0];
    const float* desc1 = (const float*)d_in[1];
    float* out = (float*)d_out;
    float* sim = out + 4 * BB * NN;

    cudaFuncSetAttribute(gemm_tc_k,
                         cudaFuncAttributeMaxDynamicSharedMemorySize,
                         SMEM_BYTES);

    {
        int warps = BB * NN + BB * MM;
        normsplit_k<<<warps / 8, 256>>>(desc0, desc1);
    }
    {
        dim3 grid(MM / 128, NN / 128, BB);
        gemm_tc_k<<<grid, 256, SMEM_BYTES>>>(sim);
    }
    {
        int warps = 2 * BB * NN;
        merge_k<<<warps / 8, 256>>>();
    }
    {
        int t = BB * NN;
        mutual_k<<<(t + 255) / 256, 256>>>(out);
    }
}

// round 13
// speedup vs baseline: 1.3151x; 1.3151x over previous
#include <cuda_runtime.h>
#include <cuda_fp16.h>
#include <math.h>
#include <stdint.h>

#define BB 8
#define NN 4096
#define MM 4096
#define DD 128
#define NTILES 32          // 4096 / 128 tiles along each reduced dim

// ---------------- scratch (device globals: no allocation allowed) ----------
__device__ __half g_h0[BB * NN * DD];   // normalized descriptors0, fp16
__device__ __half g_h1[BB * MM * DD];   // normalized descriptors1, fp16

__device__ float2 g_rp_v[BB * NN * NTILES];
__device__ int2   g_rp_i[BB * NN * NTILES];
__device__ float2 g_cp_v[BB * MM * NTILES];
__device__ int2   g_cp_i[BB * MM * NTILES];

__device__ int    g_m0raw[BB * NN];
__device__ int    g_m1raw[BB * MM];

// ---------------- small helpers ---------------------------------------------
__device__ __forceinline__ void push2(float v, int i,
                                      float& v0, int& i0, float& v1, int& i1) {
    if (v > v0) { v1 = v0; i1 = i0; v0 = v; i0 = i; }
    else if (v > v1) { v1 = v; i1 = i; }
}

__device__ __forceinline__ bool better(float va, int ia, float vb, int ib) {
    return (va > vb) || (va == vb && ia < ib);
}

__device__ __forceinline__ void merge2(float& v0, int& i0, float& v1, int& i1,
                                       float ov0, int oi0, float ov1, int oi1) {
    if (better(ov0, oi0, v0, i0)) {
        if (better(v0, i0, ov1, oi1)) { v1 = v0; i1 = i0; }
        else                          { v1 = ov1; i1 = oi1; }
        v0 = ov0; i0 = oi0;
    } else {
        if (better(ov0, oi0, v1, i1)) { v1 = ov0; i1 = oi0; }
    }
}

__device__ __forceinline__ uint32_t smem_u32(const void* p) {
    uint32_t a;
    asm("{ .reg .u64 t; cvta.to.shared.u64 t, %1; cvt.u32.u64 %0, t; }"
        : "=r"(a) : "l"(p));
    return a;
}

__device__ __forceinline__ void ldsm_x4(uint32_t& r0, uint32_t& r1,
                                        uint32_t& r2, uint32_t& r3,
                                        uint32_t addr) {
    asm volatile(
        "ldmatrix.sync.aligned.m8n8.x4.shared.b16 {%0, %1, %2, %3}, [%4];"
        : "=r"(r0), "=r"(r1), "=r"(r2), "=r"(r3) : "r"(addr));
}

__device__ __forceinline__ void mma_f16(float& c0, float& c1, float& c2, float& c3,
                                        uint32_t a0, uint32_t a1, uint32_t a2, uint32_t a3,
                                        uint32_t b0, uint32_t b1) {
    asm volatile(
        "mma.sync.aligned.m16n8k16.row.col.f32.f16.f16.f32 "
        "{%0, %1, %2, %3}, {%4, %5, %6, %7}, {%8, %9}, {%0, %1, %2, %3};"
        : "+f"(c0), "+f"(c1), "+f"(c2), "+f"(c3)
        : "r"(a0), "r"(a1), "r"(a2), "r"(a3), "r"(b0), "r"(b1));
}

__device__ __forceinline__ void cp_async16(uint32_t saddr, const void* gaddr) {
    asm volatile("cp.async.cg.shared.global [%0], [%1], 16;"
                 :: "r"(saddr), "l"(gaddr));
}
#define CP_COMMIT() asm volatile("cp.async.commit_group;" ::: "memory")
#define CP_WAIT0()  asm volatile("cp.async.wait_group 0;" ::: "memory")

// ---------------- 1. normalize -> fp16 ---------------------------------------
__global__ void normhalf_k(const float* __restrict__ d0,
                           const float* __restrict__ d1) {
    int warp = (blockIdx.x * blockDim.x + threadIdx.x) >> 5;
    int lane = threadIdx.x & 31;
    const int total = BB * NN + BB * MM;
    if (warp >= total) return;

    const float* src;
    __half* dst;
    if (warp < BB * NN) {
        src = d0 + (size_t)warp * DD;
        dst = g_h0 + (size_t)warp * DD;
    } else {
        int w = warp - BB * NN;
        src = d1 + (size_t)w * DD;
        dst = g_h1 + (size_t)w * DD;
    }

    float4 v = *(const float4*)(src + lane * 4);
    float s = v.x * v.x + v.y * v.y + v.z * v.z + v.w * v.w;
#pragma unroll
    for (int off = 16; off > 0; off >>= 1)
        s += __shfl_xor_sync(0xFFFFFFFFu, s, off);
    float inv = 1.0f / fmaxf(sqrtf(s), 1e-12f);

    __half2* d2 = (__half2*)(dst + lane * 4);
    d2[0] = __floats2half2_rn(v.x * inv, v.y * inv);
    d2[1] = __floats2half2_rn(v.z * inv, v.w * inv);
}

// ---------------- 2. fp16 mma.sync GEMM tile + fused top-2 --------------------
// One CTA = one 128x128 sim tile. 256 threads = 8 warps (2 x 4), 64x32 per warp.
// Single K=128 block: A,B tiles 128 rows x 256B (+16B pad) = 34 KB each ->
// 68 KB SMEM, 2 CTAs/SM. Per k-step: 6 ldsm.x4 + 16 mma, 8 k-steps.
// Post-MMA, SMEM is reused as fp32 staging (stride 130) for the fused
// row/col top-2 reductions and the coalesced sim write.
#define RS   272           // bytes per smem tile row (128 fp16 = 256B + 16B pad)
#define TILE_B (128 * RS)  // 34816 B per operand tile
#define OFF_A 0
#define OFF_B TILE_B
#define SMEM_BYTES (2 * TILE_B)   // 69632
#define DSTR 130                   // fp32 staging row stride (floats)

__global__ __launch_bounds__(256, 2)
void gemm_tc_k(float* __restrict__ C) {
    extern __shared__ char smem[];
    uint32_t sb = smem_u32(smem);

    const int b     = blockIdx.z;
    const int tileN = blockIdx.y;
    const int tileM = blockIdx.x;
    const int n0 = tileN * 128;    // sim row block   (A side, d0)
    const int m0 = tileM * 128;    // sim col block   (B side, d1)

    const int tid  = threadIdx.x;
    const int wid  = tid >> 5;
    const int lane = tid & 31;
    const int wm   = wid >> 2;     // 0..1 : 64-row band
    const int wn   = wid & 3;      // 0..3 : 32-col band
    const int g    = lane >> 2;    // group id
    const int t    = lane & 3;     // thread-in-group
    const int tile8 = lane >> 3;
    const int r8    = lane & 7;

    // lane-constant ldmatrix offsets (bytes) within a tile
    const uint32_t aoff = (uint32_t)(wm * 64 + (tile8 & 1) * 8 + r8) * RS
                        + (uint32_t)((tile8 >> 1) * 8) * 2;
    const uint32_t boff = (uint32_t)(wn * 32 + ((tile8 >> 1) & 1) * 8 + r8) * RS
                        + (uint32_t)((tile8 & 1) * 8) * 2;

    float acc[4][4][4];            // [mi][ni][c]
#pragma unroll
    for (int mi = 0; mi < 4; mi++)
#pragma unroll
        for (int ni = 0; ni < 4; ni++)
#pragma unroll
            for (int c = 0; c < 4; c++) acc[mi][ni][c] = 0.0f;

    // ---- async load both operand tiles (whole K) -----------------------------
    {
        const char* srcA = (const char*)(g_h0 + ((size_t)b * NN + n0) * DD);
        const char* srcB = (const char*)(g_h1 + ((size_t)b * MM + m0) * DD);
        // 2048 16B slots per tile, 256 threads -> 8 per thread per tile
#pragma unroll
        for (int it = 0; it < 8; it++) {
            int f   = it * 256 + tid;
            int row = f >> 4;          // 16 slots per row
            int q   = f & 15;
            cp_async16(sb + OFF_A + row * RS + q * 16,
                       srcA + (size_t)row * 256 + q * 16);
            cp_async16(sb + OFF_B + row * RS + q * 16,
                       srcB + (size_t)row * 256 + q * 16);
        }
        CP_COMMIT();
        CP_WAIT0();
        __syncthreads();
    }

    // ---- mainloop: 8 k-steps of 16 --------------------------------------------
#pragma unroll
    for (int ks = 0; ks < 8; ks++) {
        const uint32_t kb = ks * 32;   // byte offset of this k-step

        // A fragments
        uint32_t a[4][4];
#pragma unroll
        for (int mi = 0; mi < 4; mi++)
            ldsm_x4(a[mi][0], a[mi][1], a[mi][2], a[mi][3],
                    sb + OFF_A + aoff + mi * (16 * RS) + kb);

        // B fragments
        uint32_t bf[4][2];
#pragma unroll
        for (int nh = 0; nh < 2; nh++) {
            uint32_t r0, r1, r2, r3;
            ldsm_x4(r0, r1, r2, r3,
                    sb + OFF_B + boff + nh * (16 * RS) + kb);
            bf[nh * 2 + 0][0] = r0; bf[nh * 2 + 0][1] = r1;
            bf[nh * 2 + 1][0] = r2; bf[nh * 2 + 1][1] = r3;
        }

#pragma unroll
        for (int mi = 0; mi < 4; mi++)
#pragma unroll
            for (int ni = 0; ni < 4; ni++)
                mma_f16(acc[mi][ni][0], acc[mi][ni][1],
                        acc[mi][ni][2], acc[mi][ni][3],
                        a[mi][0], a[mi][1], a[mi][2], a[mi][3],
                        bf[ni][0], bf[ni][1]);
    }
    __syncthreads();   // operand tiles dead; smem becomes fp32 staging

    // ---- stage accumulators to SMEM (fp32, stride DSTR) -----------------------
    float* dsm = (float*)smem;
#pragma unroll
    for (int mi = 0; mi < 4; mi++) {
        int r0 = wm * 64 + mi * 16 + g;
#pragma unroll
        for (int ni = 0; ni < 4; ni++) {
            int c0 = wn * 32 + ni * 8 + 2 * t;
            *(float2*)&dsm[r0 * DSTR + c0] =
                make_float2(acc[mi][ni][0], acc[mi][ni][1]);
            *(float2*)&dsm[(r0 + 8) * DSTR + c0] =
                make_float2(acc[mi][ni][2], acc[mi][ni][3]);
        }
    }
    __syncthreads();

    // ---- parallel reductions: threads 0-127 columns, 128-255 rows -------------
    if (tid < 128) {
        int col = tid;                       // sim column m0+col
        float v0 = -2.0f, v1 = -2.0f;
        int   i0 = -1,    i1 = -1;
#pragma unroll 4
        for (int r = 0; r < 128; r++)
            push2(dsm[r * DSTR + col], n0 + r, v0, i0, v1, i1);
        size_t o = ((size_t)b * MM + m0 + col) * NTILES + tileN;
        g_cp_v[o] = make_float2(v0, v1);
        g_cp_i[o] = make_int2(i0, i1);
    } else {
        int row = tid - 128;                 // sim row n0+row
        float v0 = -2.0f, v1 = -2.0f;
        int   i0 = -1,    i1 = -1;
#pragma unroll 4
        for (int c = 0; c < 128; c += 2) {
            float2 v = *(const float2*)&dsm[row * DSTR + c];
            push2(v.x, m0 + c,     v0, i0, v1, i1);
            push2(v.y, m0 + c + 1, v0, i0, v1, i1);
        }
        size_t o = ((size_t)b * NN + n0 + row) * NTILES + tileM;
        g_rp_v[o] = make_float2(v0, v1);
        g_rp_i[o] = make_int2(i0, i1);
    }

    // ---- coalesced sim write (float2) -----------------------------------------
    {
        float* Cb = C + (size_t)b * NN * MM + (size_t)n0 * MM + m0;
#pragma unroll
        for (int it = 0; it < 32; it++) {
            int f   = it * 256 + tid;        // 8192 float2 slots
            int row = f >> 6;                // 64 float2 per row
            int u   = f & 63;
            float2 v = *(const float2*)&dsm[row * DSTR + u * 2];
            *(float2*)(Cb + (size_t)row * MM + u * 2) = v;
        }
    }
}

// ---------------- 3. merge partials + thresholds ------------------------------
__global__ void merge_k() {
    int warp = (blockIdx.x * blockDim.x + threadIdx.x) >> 5;
    int lane = threadIdx.x & 31;
    const int nrows = BB * NN;
    if (warp >= nrows + BB * MM) return;

    float2 pv;
    int2   pi;
    if (warp < nrows) {
        pv = g_rp_v[(size_t)warp * NTILES + lane];
        pi = g_rp_i[(size_t)warp * NTILES + lane];
    } else {
        size_t w = warp - nrows;
        pv = g_cp_v[w * NTILES + lane];
        pi = g_cp_i[w * NTILES + lane];
    }
    float v0 = pv.x, v1 = pv.y;
    int   i0 = pi.x, i1 = pi.y;
#pragma unroll
    for (int off = 16; off > 0; off >>= 1) {
        float ov0 = __shfl_xor_sync(0xFFFFFFFFu, v0, off);
        float ov1 = __shfl_xor_sync(0xFFFFFFFFu, v1, off);
        int   oi0 = __shfl_xor_sync(0xFFFFFFFFu, i0, off);
        int   oi1 = __shfl_xor_sync(0xFFFFFFFFu, i1, off);
        merge2(v0, i0, v1, i1, ov0, oi0, ov1, oi1);
    }
    if (lane == 0) {
        float d0 = 2.0f * (1.0f - v0);
        float d1 = 2.0f * (1.0f - v1);
        bool ok = (d0 <= 0.64f * d1) && (d0 <= 0.49f);
        int m = ok ? i0 : -1;
        if (warp < nrows) g_m0raw[warp] = m;
        else              g_m1raw[warp - nrows] = m;
    }
}

// ---------------- 4. mutual check + output write -----------------------------
// out layout (fp32): matches0 [B*N] | matches1 [B*M] | mscores0 | mscores1 | sim
__global__ void mutual_k(float* __restrict__ out) {
    int idx = blockIdx.x * blockDim.x + threadIdx.x;
    if (idx >= BB * NN) return;
    int b = idx / NN;
    int n = idx - b * NN;

    int m0 = g_m0raw[idx];
    bool good0 = (m0 > -1) && (g_m1raw[b * MM + m0] == n);
    out[idx] = good0 ? (float)m0 : -1.0f;
    out[2 * BB * NN + idx] = good0 ? 1.0f : 0.0f;

    int m1 = g_m1raw[idx];
    bool good1 = (m1 > -1) && (g_m0raw[b * NN + m1] == n);
    out[BB * NN + idx] = good1 ? (float)m1 : -1.0f;
    out[3 * BB * NN + idx] = good1 ? 1.0f : 0.0f;
}

// ---------------- launch -----------------------------------------------------
extern "C" void kernel_launch(void* const* d_in, const int* in_sizes, int n_in,
                              void* d_out, int out_size) {
    const float* desc0 = (const float*)d_in[0];
    const float* desc1 = (const float*)d_in[1];
    float* out = (float*)d_out;
    float* sim = out + 4 * BB * NN;

    cudaFuncSetAttribute(gemm_tc_k,
                         cudaFuncAttributeMaxDynamicSharedMemorySize,
                         SMEM_BYTES);

    {
        int warps = BB * NN + BB * MM;
        normhalf_k<<<warps / 8, 256>>>(desc0, desc1);
    }
    {
        dim3 grid(MM / 128, NN / 128, BB);
        gemm_tc_k<<<grid, 256, SMEM_BYTES>>>(sim);
    }
    {
        int warps = 2 * BB * NN;
        merge_k<<<warps / 8, 256>>>();
    }
    {
        int t = BB * NN;
        mutual_k<<<(t + 255) / 256, 256>>>(out);
    }
}